// round 11
// baseline (speedup 1.0000x reference)
#include <cuda_runtime.h>
#include <cuda_bf16.h>
#include <math_constants.h>

// Problem constants (fixed by the dataset)
#define NNODES 50000
#define NDIM   64
#define NEDGES 800000

// -------- device scratch (no allocation allowed) --------
__device__ int   g_deg[NNODES];
__device__ int   g_cursor[NNODES];
__device__ int   g_starts[NNODES];
__device__ int   g_total;
__device__ int2  g_edge[NEDGES];    // (src_row, bitcast(weight)) packed

// -------- kernel 1: zero counters --------
__global__ void k_zero() {
    int i = blockIdx.x * blockDim.x + threadIdx.x;
    if (i < NNODES) g_deg[i] = 0;
    if (i == 0) g_total = 0;
}

// -------- kernel 2: count in-degree (scalar: measured-best form) --------
__global__ void k_count(const int* __restrict__ edge_index) {
    int e = blockIdx.x * blockDim.x + threadIdx.x;
    if (e < NEDGES) {
        int dst = edge_index[NEDGES + e];   // edge_index[1, e]
        atomicAdd(&g_deg[dst], 1);
    }
}

// -------- kernel 3: segment offsets (block scan + global atomic base) --------
// Pre-initializes g_cursor to the segment start. Segment ordering across
// blocks is nondeterministic, but segments are disjoint and the median is
// order-invariant -> output deterministic.
#define OFF_BS 256
__global__ void k_offsets() {
    __shared__ int sh[OFF_BS];
    __shared__ int base;
    int tid = threadIdx.x;
    int gid = blockIdx.x * OFF_BS + tid;
    int v = (gid < NNODES) ? g_deg[gid] : 0;
    sh[tid] = v;
    __syncthreads();
    for (int off = 1; off < OFF_BS; off <<= 1) {
        int t = (tid >= off) ? sh[tid - off] : 0;
        __syncthreads();
        sh[tid] += t;
        __syncthreads();
    }
    if (tid == OFF_BS - 1) base = atomicAdd(&g_total, sh[tid]);
    __syncthreads();
    if (gid < NNODES) {
        int st = base + sh[tid] - v;
        g_starts[gid] = st;
        g_cursor[gid] = st;
    }
}

// -------- kernel 4: scatter (scalar: measured-best form; cursor holds start) --------
__global__ void k_scatter(const int* __restrict__ edge_index,
                          const float* __restrict__ edge_weight) {
    int e = blockIdx.x * blockDim.x + threadIdx.x;
    if (e >= NEDGES) return;
    int src = edge_index[e];
    int dst = edge_index[NEDGES + e];
    float w = edge_weight[e];
    int p = atomicAdd(&g_cursor[dst], 1);
    g_edge[p] = make_int2(src, __float_as_int(w));
}

// -------- pruned Batcher odd-even merge network, typed CAS --------
// Float CAS -> FMNMX (fma pipe). Unsigned CAS -> IMNMX.U32 (alu pipe).
// Odd warps use the monotone uint transform so the two warp populations load
// different issue pipes, ~doubling comparator throughput per SMSP.
__device__ __forceinline__ void cas_e(float& a, float& b) {
    float lo = fminf(a, b);
    float hi = fmaxf(a, b);
    a = lo; b = hi;
}
__device__ __forceinline__ void cas_e(unsigned& a, unsigned& b) {
    unsigned lo = umin(a, b);
    unsigned hi = umax(a, b);
    a = lo; b = hi;
}

template<typename T, int D, int LO, int N, int R>
struct OEMergeD {
    static __device__ __forceinline__ void run(T* v) {
        constexpr int M = R * 2;
        if constexpr (LO >= D) return;
        else if constexpr (M < N) {
            OEMergeD<T, D, LO, N, M>::run(v);
            OEMergeD<T, D, LO + R, N, M>::run(v);
#pragma unroll
            for (int i = LO + R; i + R < LO + N; i += M)
                if (i + R < D) cas_e(v[i], v[i + R]);   // folds at compile time
        } else {
            if constexpr (LO + R < D) cas_e(v[LO], v[LO + R]);
        }
    }
};

template<typename T, int D, int LO, int N>
struct OESortD {
    static __device__ __forceinline__ void run(T* v) {
        if constexpr (LO >= D || N <= 1) return;
        else {
            constexpr int M = N / 2;
            OESortD<T, D, LO, M>::run(v);
            OESortD<T, D, LO + M, M>::run(v);
            OEMergeD<T, D, LO, N, 1>::run(v);
        }
    }
};

// Monotone (order-preserving) float <-> uint key transform.
__device__ __forceinline__ unsigned f2key(float f) {
    int i = __float_as_int(f);
    return (unsigned)(i ^ ((i >> 31) | 0x80000000));
}
__device__ __forceinline__ float key2f(unsigned u) {
    int j = (int)u;
    int m = ((~j) >> 31) | 0x80000000;
    return __int_as_float(j ^ m);
}

// -------- float-domain gather + sort + k-select (fma pipe) --------
template<int D>
__device__ __forceinline__ float median_reg_f(const int2* __restrict__ stage,
                                              const float* __restrict__ x,
                                              int d, int deg, int k) {
    constexpr int P = (D <= 8) ? 8 : (D <= 16) ? 16 : 32;
    float v[D];
#pragma unroll
    for (int j = 0; j < D; j++) {
        if (j < deg) {
            int2 e = stage[j];
            v[j] = x[e.x * NDIM + d] * __int_as_float(e.y);
        } else {
            v[j] = CUDART_INF_F;
        }
    }
    OESortD<float, D, 0, P>::run(v);
    float r = v[0];
#pragma unroll
    for (int i = 1; i < D; i++) r = (k == i) ? v[i] : r;
    return r;
}

// -------- uint-domain gather + sort + k-select (alu pipe) --------
template<int D>
__device__ __forceinline__ float median_reg_u(const int2* __restrict__ stage,
                                              const float* __restrict__ x,
                                              int d, int deg, int k) {
    constexpr int P = (D <= 8) ? 8 : (D <= 16) ? 16 : 32;
    unsigned v[D];
#pragma unroll
    for (int j = 0; j < D; j++) {
        if (j < deg) {
            int2 e = stage[j];
            v[j] = f2key(x[e.x * NDIM + d] * __int_as_float(e.y));
        } else {
            v[j] = 0xFFFFFFFFu;   // >= key(+inf): sorts to end, never selected
        }
    }
    OESortD<unsigned, D, 0, P>::run(v);
    unsigned r = v[0];
#pragma unroll
    for (int i = 1; i < D; i++) r = (k == i) ? v[i] : r;
    return key2f(r);
}

// -------- kernel 5: per-node per-channel lower median --------
// 4 nodes/block, 2 warps/node, warps independent (__syncwarp only).
// Even warps sort in float (FMNMX/fma pipe), odd warps in uint keys
// (IMNMX/alu pipe) -> per-SMSP comparator throughput ~doubles.
#define NODES_PER_BLK 4
__global__ void __launch_bounds__(NDIM * NODES_PER_BLK)
k_median(const float* __restrict__ x, float* __restrict__ out) {
    __shared__ int2 stage_s[NODES_PER_BLK * 2][32];

    int n = blockIdx.x * NODES_PER_BLK + threadIdx.y;
    int d = threadIdx.x;
    if (n >= NNODES) return;

    int deg = g_deg[n];
    if (deg == 0) {
        out[n * NDIM + d] = 0.0f;
        return;
    }
    int s = g_starts[n];
    int k = (deg - 1) >> 1;

    if (deg <= 32) {
        int wi   = threadIdx.y * 2 + (d >> 5);
        int lane = d & 31;
        if (lane < deg) stage_s[wi][lane] = g_edge[s + lane];
        __syncwarp();
        const int2* st = stage_s[wi];

        float med;
        if (wi & 1) {   // alu-pipe warps
            if      (deg <= 8)  med = median_reg_u<8> (st, x, d, deg, k);
            else if (deg <= 12) med = median_reg_u<12>(st, x, d, deg, k);
            else if (deg <= 16) med = median_reg_u<16>(st, x, d, deg, k);
            else if (deg <= 20) med = median_reg_u<20>(st, x, d, deg, k);
            else if (deg <= 24) med = median_reg_u<24>(st, x, d, deg, k);
            else if (deg <= 28) med = median_reg_u<28>(st, x, d, deg, k);
            else                med = median_reg_u<32>(st, x, d, deg, k);
        } else {        // fma-pipe warps
            if      (deg <= 8)  med = median_reg_f<8> (st, x, d, deg, k);
            else if (deg <= 12) med = median_reg_f<12>(st, x, d, deg, k);
            else if (deg <= 16) med = median_reg_f<16>(st, x, d, deg, k);
            else if (deg <= 20) med = median_reg_f<20>(st, x, d, deg, k);
            else if (deg <= 24) med = median_reg_f<24>(st, x, d, deg, k);
            else if (deg <= 28) med = median_reg_f<28>(st, x, d, deg, k);
            else                med = median_reg_f<32>(st, x, d, deg, k);
        }
        out[n * NDIM + d] = med;
    } else {
        // Rare path (P(deg>32) ~ 1e-4 per node): global rank-count selection.
        float med = 0.0f;
        for (int i = 0; i < deg; i++) {
            int2 ei = g_edge[s + i];
            float vi = x[ei.x * NDIM + d] * __int_as_float(ei.y);
            int less = 0, eq = 0;
            for (int j = 0; j < deg; j++) {
                int2 ej = g_edge[s + j];
                float vj = x[ej.x * NDIM + d] * __int_as_float(ej.y);
                less += (vj < vi);
                eq   += (vj == vi);
            }
            if (less <= k && k < less + eq) { med = vi; break; }
        }
        out[n * NDIM + d] = med;
    }
}

extern "C" void kernel_launch(void* const* d_in, const int* in_sizes, int n_in,
                              void* d_out, int out_size) {
    const float* x           = (const float*)d_in[0];
    const int*   edge_index  = (const int*)d_in[1];
    const float* edge_weight = (const float*)d_in[2];
    float*       out         = (float*)d_out;

    (void)in_sizes; (void)n_in; (void)out_size;

    k_zero   <<<(NNODES + 255) / 256, 256>>>();
    k_count  <<<(NEDGES + 255) / 256, 256>>>(edge_index);
    k_offsets<<<(NNODES + OFF_BS - 1) / OFF_BS, OFF_BS>>>();
    k_scatter<<<(NEDGES + 255) / 256, 256>>>(edge_index, edge_weight);

    dim3 mblk(NDIM, NODES_PER_BLK);
    k_median <<<(NNODES + NODES_PER_BLK - 1) / NODES_PER_BLK, mblk>>>(x, out);
}

// round 14
// speedup vs baseline: 1.3798x; 1.3798x over previous
#include <cuda_runtime.h>
#include <cuda_bf16.h>
#include <math_constants.h>

// Problem constants (fixed by the dataset)
#define NNODES 50000
#define NDIM   64
#define NEDGES 800000

// -------- device scratch (no allocation allowed) --------
__device__ int   g_deg[NNODES];
__device__ int   g_cursor[NNODES];
__device__ int   g_starts[NNODES];
__device__ int   g_total;
__device__ int2  g_edge[NEDGES];    // (src_row, bitcast(weight)) packed

// -------- kernel 1: zero counters --------
__global__ void k_zero() {
    int i = blockIdx.x * blockDim.x + threadIdx.x;
    if (i < NNODES) g_deg[i] = 0;
    if (i == 0) g_total = 0;
}

// -------- kernel 2: count in-degree (scalar: measured-best form) --------
__global__ void k_count(const int* __restrict__ edge_index) {
    int e = blockIdx.x * blockDim.x + threadIdx.x;
    if (e < NEDGES) {
        int dst = edge_index[NEDGES + e];   // edge_index[1, e]
        atomicAdd(&g_deg[dst], 1);
    }
}

// -------- kernel 3: segment offsets (block scan + global atomic base) --------
// Pre-initializes g_cursor to the segment start (measured: scatter 15.4->14.8).
// Segment ordering across blocks is nondeterministic, but segments are
// disjoint and the median is order-invariant -> output deterministic.
#define OFF_BS 256
__global__ void k_offsets() {
    __shared__ int sh[OFF_BS];
    __shared__ int base;
    int tid = threadIdx.x;
    int gid = blockIdx.x * OFF_BS + tid;
    int v = (gid < NNODES) ? g_deg[gid] : 0;
    sh[tid] = v;
    __syncthreads();
    for (int off = 1; off < OFF_BS; off <<= 1) {
        int t = (tid >= off) ? sh[tid - off] : 0;
        __syncthreads();
        sh[tid] += t;
        __syncthreads();
    }
    if (tid == OFF_BS - 1) base = atomicAdd(&g_total, sh[tid]);
    __syncthreads();
    if (gid < NNODES) {
        int st = base + sh[tid] - v;
        g_starts[gid] = st;
        g_cursor[gid] = st;
    }
}

// -------- kernel 4: scatter (scalar, cursor holds segment start) --------
__global__ void k_scatter(const int* __restrict__ edge_index,
                          const float* __restrict__ edge_weight) {
    int e = blockIdx.x * blockDim.x + threadIdx.x;
    if (e >= NEDGES) return;
    int src = edge_index[e];
    int dst = edge_index[NEDGES + e];
    float w = edge_weight[e];
    int p = atomicAdd(&g_cursor[dst], 1);
    g_edge[p] = make_int2(src, __float_as_int(w));
}

// -------- pruned Batcher odd-even merge network (measured-best R7 form) --------
// Ascending comparators only. With +inf on wires >= deg, those wires hold
// +inf forever, so comparators with high wire >= D fold away at compile time.
__device__ __forceinline__ void cas_f(float& a, float& b) {
    float lo = fminf(a, b);
    float hi = fmaxf(a, b);
    a = lo; b = hi;
}

template<int D, int LO, int N, int R>
struct OEMergeD {
    static __device__ __forceinline__ void run(float* v) {
        constexpr int M = R * 2;
        if constexpr (LO >= D) return;
        else if constexpr (M < N) {
            OEMergeD<D, LO, N, M>::run(v);
            OEMergeD<D, LO + R, N, M>::run(v);
#pragma unroll
            for (int i = LO + R; i + R < LO + N; i += M)
                if (i + R < D) cas_f(v[i], v[i + R]);   // folds at compile time
        } else {
            if constexpr (LO + R < D) cas_f(v[LO], v[LO + R]);
        }
    }
};

template<int D, int LO, int N>
struct OESortD {
    static __device__ __forceinline__ void run(float* v) {
        if constexpr (LO >= D || N <= 1) return;
        else {
            constexpr int M = N / 2;
            OESortD<D, LO, M>::run(v);
            OESortD<D, LO + M, M>::run(v);
            OEMergeD<D, LO, N, 1>::run(v);
        }
    }
};

// -------- register gather + pruned sort + k-select for degree bucket D --------
template<int D>
__device__ __forceinline__ float median_reg(const int2* __restrict__ stage,
                                            const float* __restrict__ x,
                                            int d, int deg, int k) {
    constexpr int P = (D <= 8) ? 8 : (D <= 16) ? 16 : 32;   // parent pow2 network
    float v[D];
#pragma unroll
    for (int j = 0; j < D; j++) {
        if (j < deg) {
            int2 e = stage[j];
            v[j] = x[e.x * NDIM + d] * __int_as_float(e.y);
        } else {
            v[j] = CUDART_INF_F;
        }
    }
    OESortD<D, 0, P>::run(v);
    float r = v[0];
#pragma unroll
    for (int i = 1; i < D; i++) r = (k == i) ? v[i] : r;
    return r;
}

// -------- kernel 5: per-node per-channel lower median (R7 verbatim) --------
// 4 nodes/block, 2 warps/node. Warps are fully independent: each warp stages
// its node's edge list into its own smem slice (__syncwarp only, no block
// barriers), so degree buckets can differ freely across warps.
#define NODES_PER_BLK 4
__global__ void __launch_bounds__(NDIM * NODES_PER_BLK)
k_median(const float* __restrict__ x, float* __restrict__ out) {
    __shared__ int2 stage_s[NODES_PER_BLK * 2][32];

    int n = blockIdx.x * NODES_PER_BLK + threadIdx.y;
    int d = threadIdx.x;
    if (n >= NNODES) return;

    int deg = g_deg[n];
    if (deg == 0) {
        out[n * NDIM + d] = 0.0f;
        return;
    }
    int s = g_starts[n];
    int k = (deg - 1) >> 1;

    if (deg <= 32) {
        int wi   = threadIdx.y * 2 + (d >> 5);
        int lane = d & 31;
        if (lane < deg) stage_s[wi][lane] = g_edge[s + lane];
        __syncwarp();
        const int2* st = stage_s[wi];

        float med;
        if      (deg <= 8)  med = median_reg<8> (st, x, d, deg, k);
        else if (deg <= 12) med = median_reg<12>(st, x, d, deg, k);
        else if (deg <= 16) med = median_reg<16>(st, x, d, deg, k);
        else if (deg <= 20) med = median_reg<20>(st, x, d, deg, k);
        else if (deg <= 24) med = median_reg<24>(st, x, d, deg, k);
        else if (deg <= 28) med = median_reg<28>(st, x, d, deg, k);
        else                med = median_reg<32>(st, x, d, deg, k);
        out[n * NDIM + d] = med;
    } else {
        // Rare path (P(deg>32) ~ 1e-4 per node): global rank-count selection.
        float med = 0.0f;
        for (int i = 0; i < deg; i++) {
            int2 ei = g_edge[s + i];
            float vi = x[ei.x * NDIM + d] * __int_as_float(ei.y);
            int less = 0, eq = 0;
            for (int j = 0; j < deg; j++) {
                int2 ej = g_edge[s + j];
                float vj = x[ej.x * NDIM + d] * __int_as_float(ej.y);
                less += (vj < vi);
                eq   += (vj == vi);
            }
            if (less <= k && k < less + eq) { med = vi; break; }
        }
        out[n * NDIM + d] = med;
    }
}

extern "C" void kernel_launch(void* const* d_in, const int* in_sizes, int n_in,
                              void* d_out, int out_size) {
    const float* x           = (const float*)d_in[0];
    const int*   edge_index  = (const int*)d_in[1];
    const float* edge_weight = (const float*)d_in[2];
    float*       out         = (float*)d_out;

    (void)in_sizes; (void)n_in; (void)out_size;

    k_zero   <<<(NNODES + 255) / 256, 256>>>();
    k_count  <<<(NEDGES + 255) / 256, 256>>>(edge_index);
    k_offsets<<<(NNODES + OFF_BS - 1) / OFF_BS, OFF_BS>>>();
    k_scatter<<<(NEDGES + 255) / 256, 256>>>(edge_index, edge_weight);

    dim3 mblk(NDIM, NODES_PER_BLK);
    k_median <<<(NNODES + NODES_PER_BLK - 1) / NODES_PER_BLK, mblk>>>(x, out);
}

// round 17
// speedup vs baseline: 1.4082x; 1.0206x over previous
#include <cuda_runtime.h>
#include <cuda_bf16.h>
#include <math_constants.h>

// Problem constants (fixed by the dataset)
#define NNODES 50000
#define NDIM   64
#define NEDGES 800000

// -------- device scratch (no allocation allowed) --------
__device__ int   g_deg[NNODES];
__device__ int   g_pos[NEDGES];     // within-segment rank of each edge
__device__ int   g_starts[NNODES];
__device__ int   g_total;
__device__ int2  g_edge[NEDGES];    // (src_row, bitcast(weight)) packed

// -------- kernel 1: zero counters --------
__global__ void k_zero() {
    int i = blockIdx.x * blockDim.x + threadIdx.x;
    if (i < NNODES) g_deg[i] = 0;
    if (i == 0) g_total = 0;
}

// -------- kernel 2: count in-degree AND record within-segment rank --------
// The atomicAdd return value is the edge's position inside its destination
// segment; recording it makes the scatter pass atomic-free.
__global__ void k_count(const int* __restrict__ edge_index) {
    int e = blockIdx.x * blockDim.x + threadIdx.x;
    if (e < NEDGES) {
        int dst = edge_index[NEDGES + e];   // edge_index[1, e]
        g_pos[e] = atomicAdd(&g_deg[dst], 1);
    }
}

// -------- kernel 3: segment offsets (block scan + global atomic base) --------
// Segment ordering across blocks is nondeterministic, but segments are
// disjoint and the median is order-invariant -> output deterministic.
#define OFF_BS 256
__global__ void k_offsets() {
    __shared__ int sh[OFF_BS];
    __shared__ int base;
    int tid = threadIdx.x;
    int gid = blockIdx.x * OFF_BS + tid;
    int v = (gid < NNODES) ? g_deg[gid] : 0;
    sh[tid] = v;
    __syncthreads();
    for (int off = 1; off < OFF_BS; off <<= 1) {
        int t = (tid >= off) ? sh[tid - off] : 0;
        __syncthreads();
        sh[tid] += t;
        __syncthreads();
    }
    if (tid == OFF_BS - 1) base = atomicAdd(&g_total, sh[tid]);
    __syncthreads();
    if (gid < NNODES) g_starts[gid] = base + sh[tid] - v;
}

// -------- kernel 4: scatter — ATOMIC-FREE (rank precomputed in k_count) --------
__global__ void k_scatter(const int* __restrict__ edge_index,
                          const float* __restrict__ edge_weight) {
    int e = blockIdx.x * blockDim.x + threadIdx.x;
    if (e >= NEDGES) return;
    int src = edge_index[e];
    int dst = edge_index[NEDGES + e];
    float w = edge_weight[e];
    int idx = g_starts[dst] + g_pos[e];
    g_edge[idx] = make_int2(src, __float_as_int(w));
}

// -------- pruned Batcher odd-even merge network (measured-best R7 form) --------
// Ascending comparators only. With +inf on wires >= deg, those wires hold
// +inf forever, so comparators with high wire >= D fold away at compile time.
__device__ __forceinline__ void cas_f(float& a, float& b) {
    float lo = fminf(a, b);
    float hi = fmaxf(a, b);
    a = lo; b = hi;
}

template<int D, int LO, int N, int R>
struct OEMergeD {
    static __device__ __forceinline__ void run(float* v) {
        constexpr int M = R * 2;
        if constexpr (LO >= D) return;
        else if constexpr (M < N) {
            OEMergeD<D, LO, N, M>::run(v);
            OEMergeD<D, LO + R, N, M>::run(v);
#pragma unroll
            for (int i = LO + R; i + R < LO + N; i += M)
                if (i + R < D) cas_f(v[i], v[i + R]);   // folds at compile time
        } else {
            if constexpr (LO + R < D) cas_f(v[LO], v[LO + R]);
        }
    }
};

template<int D, int LO, int N>
struct OESortD {
    static __device__ __forceinline__ void run(float* v) {
        if constexpr (LO >= D || N <= 1) return;
        else {
            constexpr int M = N / 2;
            OESortD<D, LO, M>::run(v);
            OESortD<D, LO + M, M>::run(v);
            OEMergeD<D, LO, N, 1>::run(v);
        }
    }
};

// -------- register gather + pruned sort + k-select for degree bucket D --------
template<int D>
__device__ __forceinline__ float median_reg(const int2* __restrict__ stage,
                                            const float* __restrict__ x,
                                            int d, int deg, int k) {
    constexpr int P = (D <= 8) ? 8 : (D <= 16) ? 16 : 32;   // parent pow2 network
    float v[D];
#pragma unroll
    for (int j = 0; j < D; j++) {
        if (j < deg) {
            int2 e = stage[j];
            v[j] = x[e.x * NDIM + d] * __int_as_float(e.y);
        } else {
            v[j] = CUDART_INF_F;
        }
    }
    OESortD<D, 0, P>::run(v);
    float r = v[0];
#pragma unroll
    for (int i = 1; i < D; i++) r = (k == i) ? v[i] : r;
    return r;
}

// -------- kernel 5: per-node per-channel lower median (R7 verbatim) --------
// 4 nodes/block, 2 warps/node. Warps are fully independent: each warp stages
// its node's edge list into its own smem slice (__syncwarp only, no block
// barriers), so degree buckets can differ freely across warps.
#define NODES_PER_BLK 4
__global__ void __launch_bounds__(NDIM * NODES_PER_BLK)
k_median(const float* __restrict__ x, float* __restrict__ out) {
    __shared__ int2 stage_s[NODES_PER_BLK * 2][32];

    int n = blockIdx.x * NODES_PER_BLK + threadIdx.y;
    int d = threadIdx.x;
    if (n >= NNODES) return;

    int deg = g_deg[n];
    if (deg == 0) {
        out[n * NDIM + d] = 0.0f;
        return;
    }
    int s = g_starts[n];
    int k = (deg - 1) >> 1;

    if (deg <= 32) {
        int wi   = threadIdx.y * 2 + (d >> 5);
        int lane = d & 31;
        if (lane < deg) stage_s[wi][lane] = g_edge[s + lane];
        __syncwarp();
        const int2* st = stage_s[wi];

        float med;
        if      (deg <= 8)  med = median_reg<8> (st, x, d, deg, k);
        else if (deg <= 12) med = median_reg<12>(st, x, d, deg, k);
        else if (deg <= 16) med = median_reg<16>(st, x, d, deg, k);
        else if (deg <= 20) med = median_reg<20>(st, x, d, deg, k);
        else if (deg <= 24) med = median_reg<24>(st, x, d, deg, k);
        else if (deg <= 28) med = median_reg<28>(st, x, d, deg, k);
        else                med = median_reg<32>(st, x, d, deg, k);
        out[n * NDIM + d] = med;
    } else {
        // Rare path (P(deg>32) ~ 1e-4 per node): global rank-count selection.
        float med = 0.0f;
        for (int i = 0; i < deg; i++) {
            int2 ei = g_edge[s + i];
            float vi = x[ei.x * NDIM + d] * __int_as_float(ei.y);
            int less = 0, eq = 0;
            for (int j = 0; j < deg; j++) {
                int2 ej = g_edge[s + j];
                float vj = x[ej.x * NDIM + d] * __int_as_float(ej.y);
                less += (vj < vi);
                eq   += (vj == vi);
            }
            if (less <= k && k < less + eq) { med = vi; break; }
        }
        out[n * NDIM + d] = med;
    }
}

extern "C" void kernel_launch(void* const* d_in, const int* in_sizes, int n_in,
                              void* d_out, int out_size) {
    const float* x           = (const float*)d_in[0];
    const int*   edge_index  = (const int*)d_in[1];
    const float* edge_weight = (const float*)d_in[2];
    float*       out         = (float*)d_out;

    (void)in_sizes; (void)n_in; (void)out_size;

    k_zero   <<<(NNODES + 255) / 256, 256>>>();
    k_count  <<<(NEDGES + 255) / 256, 256>>>(edge_index);
    k_offsets<<<(NNODES + OFF_BS - 1) / OFF_BS, OFF_BS>>>();
    k_scatter<<<(NEDGES + 255) / 256, 256>>>(edge_index, edge_weight);

    dim3 mblk(NDIM, NODES_PER_BLK);
    k_median <<<(NNODES + NODES_PER_BLK - 1) / NODES_PER_BLK, mblk>>>(x, out);
}